// round 13
// baseline (speedup 1.0000x reference)
#include <cuda_runtime.h>
#include <cuda_fp16.h>
#include <cstdint>

// adder2d: out[b,f,l] = -sum_{c,kh,kw} |W[f,c,kh,kw] - xpad[b,c,...]|
// ReLU identity: sum|w-x| = (SW[f] - SXpatch[b,l]) + 2*sum relu(x-w)
//   => out = (SX - SW) - 2*sum relu(x-w).
// init_out writes SX - SW; main kernel RED-adds -2*relu_sum.
// Inner loop: fma.rn.relu.f16x2 (x*1 + (-w)) + add.rn.f16x2 -> 2 fma-pipe instrs.
// Grid: 8 fgroups(16 filters) x 16 b x 8 chunks(16ch) = 1024 CTAs, occ 6 (1.15 waves).

#define BATCH 16
#define CIN   128
#define HW    28
#define LSP   784
#define FOUT  128
#define NT    224
#define CPC   16
#define NCHQ  8
#define SROW  36
#define TROWS 30
#define NFP   (FOUT / 2)   // 64 filter pairs

typedef unsigned int u32;

__device__ u32   g_xd[BATCH * CIN * LSP];  // dup fp16x2 of x: (h(v), h(v))
__device__ u32   g_wq[CIN * 9 * NFP];      // [(c*9+kk)][fp] = (h(-W[2fp]), h(-W[2fp+1]))
__device__ float g_sw[FOUT];               // per-filter weight sum
__device__ float g_sx[BATCH * LSP];        // per-(b,l) 3x3 patch sum of channel-summed x

// acc2 += relu(x2 - w2)   (HFMA2.relu + HADD2 : 2 fma-pipe instrs)
__device__ __forceinline__ void relu_acc(u32& acc, u32 p2, u32 one, u32 nw2) {
    asm("{\n\t"
        ".reg .b32 d;\n\t"
        "fma.rn.relu.f16x2 d, %1, %2, %3;\n\t"
        "add.rn.f16x2 %0, %0, d;\n\t"
        "}"
        : "+r"(acc) : "r"(p2), "r"(one), "r"(nw2));
}

__global__ void prep_x_kernel(const float* __restrict__ x) {
    int i = blockIdx.x * 1024 + threadIdx.x;   // over 16*128*784
    float v = x[i];
    __half2 hv = __floats2half2_rn(v, v);
    g_xd[i] = *reinterpret_cast<u32*>(&hv);
}

__global__ void prep_w_kernel(const float* __restrict__ Wt) {
    int i = blockIdx.x * 256 + threadIdx.x;    // over 128*9*64 = 73728
    if (i >= CIN * 9 * NFP) return;
    int fp = i & (NFP - 1);
    int ck = i >> 6;                           // c*9 + kk
    const float* wp = Wt + (size_t)(2 * fp) * (CIN * 9) + ck;
    __half2 hw = __floats2half2_rn(-wp[0], -wp[CIN * 9]);
    g_wq[(size_t)ck * NFP + fp] = *reinterpret_cast<u32*>(&hw);
}

// one block per filter: parallel tree-reduce 1152 weights
__global__ void prep_sw_kernel(const float* __restrict__ Wt) {
    __shared__ float red[256];
    const int f = blockIdx.x;
    const int t = threadIdx.x;
    const float* wp = Wt + (size_t)f * (CIN * 9);
    float s = 0.f;
    for (int k = t; k < CIN * 9; k += 256) s += wp[k];
    red[t] = s;
    __syncthreads();
#pragma unroll
    for (int d = 128; d > 0; d >>= 1) {
        if (t < d) red[t] += red[t + d];
        __syncthreads();
    }
    if (t == 0) g_sw[f] = red[0];
}

__global__ void prep_sx_kernel(const float* __restrict__ x) {
    __shared__ float cs[LSP];
    const int b = blockIdx.x;
    const int l = threadIdx.x;                 // 784 threads, coalesced loads
    const float* xb = x + (size_t)b * CIN * LSP + l;
    float s = 0.f;
#pragma unroll 8
    for (int c = 0; c < CIN; ++c) s += xb[(size_t)c * LSP];
    cs[l] = s;
    __syncthreads();
    int h = l / HW, w = l - h * HW;
    float bs = 0.f;
#pragma unroll
    for (int dh = -1; dh <= 1; ++dh)
#pragma unroll
        for (int dw = -1; dw <= 1; ++dw) {
            int hh = h + dh, ww = w + dw;
            if (hh >= 0 && hh < HW && ww >= 0 && ww < HW)
                bs += cs[hh * HW + ww];
        }
    g_sx[b * LSP + l] = bs;
}

// out[b,f,l] = SX[b,l] - SW[f]
__global__ void init_out_kernel(float* __restrict__ out) {
    int i  = blockIdx.x * 1024 + threadIdx.x;  // over 1,605,632
    int l  = i % LSP;
    int fb = i / LSP;
    int f  = fb & (FOUT - 1);
    int b  = fb >> 7;
    out[i] = g_sx[b * LSP + l] - g_sw[f];
}

__global__ __launch_bounds__(NT, 6)
void adder2d_kernel(float* __restrict__ out) {
    __shared__ u32 xs[2][TROWS * SROW];   // dup fp16x2 tiles, 8640 B
    __shared__ u32 ws[CPC * 9 * 8];       // [c*9+kk][pair0..7] = -w fp16x2, 4608 B

    const int b   = blockIdx.y;
    const int fp0 = blockIdx.x * 8;       // 8 filter pairs per CTA
    const int cq  = blockIdx.z;
    const int t   = threadIdx.x;
    const int tl  = (t < 112) ? t : (t - 112);
    const int g   = (t < 112) ? 0 : 4;
    const int h   = tl >> 2;
    const int q   = tl & 3;
    const int cb  = h * SROW + 7 * q;
    const u32 ONE = 0x3C003C00u;          // (1.h, 1.h)

    for (int i = t; i < 2 * TROWS * SROW; i += NT)
        (&xs[0][0])[i] = 0u;

    {   // stage -w: 16ch x 9kk x 8 pairs = 1152 u32, coalesced
        const u32* wp = g_wq + (size_t)(cq * CPC * 9) * NFP + fp0;
        for (int i = t; i < CPC * 9 * 8; i += NT) {
            int p  = i & 7;
            int ck = i >> 3;
            ws[i] = wp[(size_t)ck * NFP + p];
        }
    }

    u32 offsA, offsB;
    {
        u32 o[4];
#pragma unroll
        for (int j = 0; j < 4; ++j) {
            int l = t + NT * j;
            if (l < LSP) {
                int hh = l / HW;
                int ww = l - hh * HW;
                o[j] = (hh + 1) * SROW + (ww + 1);
            } else o[j] = 0;
        }
        offsA = o[0] | (o[1] << 16);
        offsB = o[2] | (o[3] << 16);
    }

    const u32* xg = g_xd + ((size_t)b * CIN + (size_t)cq * CPC) * LSP;
    u32 r[4];
#pragma unroll
    for (int j = 0; j < 3; ++j) r[j] = xg[t + NT * j];
    if (t < 112) r[3] = xg[t + NT * 3];

    u32 acc[4][7];
#pragma unroll
    for (int p = 0; p < 4; ++p)
#pragma unroll
        for (int j = 0; j < 7; ++j) acc[p][j] = 0u;

    __syncthreads();

#pragma unroll 1
    for (int ch = 0; ch < CPC; ++ch) {
        const int buf = ch & 1;
        xs[buf][offsA & 0xFFFF] = r[0];
        xs[buf][offsA >> 16]    = r[1];
        xs[buf][offsB & 0xFFFF] = r[2];
        if (t < 112) xs[buf][offsB >> 16] = r[3];
        if (ch + 1 < CPC) {
            const u32* xn = xg + (size_t)(ch + 1) * LSP;
#pragma unroll
            for (int j = 0; j < 3; ++j) r[j] = xn[t + NT * j];
            if (t < 112) r[3] = xn[t + NT * 3];
        }
        __syncthreads();

        const u32* wrow = ws + ch * 72;
#pragma unroll
        for (int kh = 0; kh < 3; ++kh) {
            u32 xv[9];
#pragma unroll
            for (int i = 0; i < 9; ++i)
                xv[i] = xs[buf][cb + kh * SROW + i];
#pragma unroll
            for (int kw = 0; kw < 3; ++kw) {
                uint4 wv = *reinterpret_cast<const uint4*>(&wrow[(kh * 3 + kw) * 8 + g]);
#pragma unroll
                for (int j = 0; j < 7; ++j) {
                    relu_acc(acc[0][j], xv[j + kw], ONE, wv.x);
                    relu_acc(acc[1][j], xv[j + kw], ONE, wv.y);
                    relu_acc(acc[2][j], xv[j + kw], ONE, wv.z);
                    relu_acc(acc[3][j], xv[j + kw], ONE, wv.w);
                }
            }
        }
    }

    // epilogue: out += -2 * relu_sum (RED; 8 contributions per output)
    float* ob = out + ((size_t)b * FOUT + 2 * (fp0 + g)) * LSP + h * HW + 7 * q;
#pragma unroll
    for (int p = 0; p < 4; ++p) {
        float* o0 = ob + (size_t)(2 * p) * LSP;
        float* o1 = o0 + LSP;
#pragma unroll
        for (int j = 0; j < 7; ++j) {
            float2 v = __half22float2(*reinterpret_cast<__half2*>(&acc[p][j]));
            atomicAdd(&o0[j], -2.0f * v.x);
            atomicAdd(&o1[j], -2.0f * v.y);
        }
    }
}

extern "C" void kernel_launch(void* const* d_in, const int* in_sizes, int n_in,
                              void* d_out, int out_size) {
    const float* x = (const float*)d_in[0];
    const float* W = (const float*)d_in[1];
    if (n_in >= 2 && in_sizes[0] == FOUT * CIN * 9 && in_sizes[1] == BATCH * CIN * LSP) {
        const float* tmp = x; x = W; W = tmp;
    }
    float* out = (float*)d_out;

    prep_x_kernel<<<BATCH * CIN * LSP / 1024, 1024>>>(x);
    prep_w_kernel<<<(CIN * 9 * NFP + 255) / 256, 256>>>(W);
    prep_sw_kernel<<<FOUT, 256>>>(W);
    prep_sx_kernel<<<BATCH, LSP>>>(x);
    init_out_kernel<<<BATCH * FOUT * LSP / 1024, 1024>>>(out);

    dim3 grid(FOUT / 16, BATCH, NCHQ);   // 8 x 16 x 8 = 1024 CTAs
    adder2d_kernel<<<grid, NT>>>(out);
}

// round 15
// speedup vs baseline: 1.6597x; 1.6597x over previous
#include <cuda_runtime.h>
#include <cuda_fp16.h>
#include <cstdint>

// adder2d: out[b,f,l] = -sum_{c,kh,kw} |W[f,c,kh,kw] - xpad[b,c,...]|
// fp16x2 inner math (packed = 2 filters), AND-form abs, fp32 via gmem RED.
// Grid: 8 fgroups(16 filters) x 16 b x 8 chunks(16ch) = 1024 CTAs, occ 5.
// CTA 224 thr: t<112 -> pairs 0..3, t>=112 -> pairs 4..7; 7 pixels x 4 pairs each.
// x pre-duplicated to fp16x2 (prep_x), W pre-packed/negated-free (prep_w).
// PAIR-buffered tiles: 4 buffers, ONE __syncthreads per 2 channels (8 total).

#define BATCH 16
#define CIN   128
#define HW    28
#define LSP   784
#define FOUT  128
#define NT    224
#define CPC   16
#define NCHQ  8
#define SROW  36
#define TROWS 30
#define NFP   (FOUT / 2)   // 64 filter pairs

typedef unsigned int u32;

__device__ u32 g_xd[BATCH * CIN * LSP];   // dup fp16x2 of x: (h(v), h(v))
__device__ u32 g_wq[CIN * 9 * NFP];       // [(c*9+kk)][fp] = (h(W[2fp]), h(W[2fp+1]))

// acc2 += | w2 - p2 |  (HFMA2 + LOP3 + HADD2 — proven best mix)
__device__ __forceinline__ void absdiff_acc(u32& acc, u32 p2, u32 negone, u32 w2) {
    asm("{\n\t"
        ".reg .b32 d;\n\t"
        "fma.rn.f16x2 d, %1, %2, %3;\n\t"
        "and.b32 d, d, 0x7FFF7FFF;\n\t"
        "add.rn.f16x2 %0, %0, d;\n\t"
        "}"
        : "+r"(acc) : "r"(p2), "r"(negone), "r"(w2));
}

__global__ void zero_out_kernel(float4* o) {
    o[(size_t)blockIdx.x * 1024 + threadIdx.x] = make_float4(0.f, 0.f, 0.f, 0.f);
}

__global__ void prep_x_kernel(const float* __restrict__ x) {
    int i = blockIdx.x * 1024 + threadIdx.x;   // over 16*128*784 = 1,605,632
    float v = x[i];
    __half2 hv = __floats2half2_rn(v, v);
    g_xd[i] = *reinterpret_cast<u32*>(&hv);
}

__global__ void prep_w_kernel(const float* __restrict__ Wt) {
    int i = blockIdx.x * 256 + threadIdx.x;    // over 128*9*64 = 73728
    if (i >= CIN * 9 * NFP) return;
    int fp = i & (NFP - 1);
    int ck = i >> 6;                           // c*9 + kk
    const float* wp = Wt + (size_t)(2 * fp) * (CIN * 9) + ck;
    __half2 hw = __floats2half2_rn(wp[0], wp[CIN * 9]);
    g_wq[(size_t)ck * NFP + fp] = *reinterpret_cast<u32*>(&hw);
}

__global__ __launch_bounds__(NT, 5)
void adder2d_kernel(float* __restrict__ out) {
    __shared__ u32 xs[4][TROWS * SROW];   // 4 dup fp16x2 tiles, 17280 B
    __shared__ u32 ws[CPC * 9 * 8];       // [c*9+kk][pair0..7], 4608 B

    const int b   = blockIdx.y;
    const int fp0 = blockIdx.x * 8;       // 8 filter pairs per CTA
    const int cq  = blockIdx.z;
    const int t   = threadIdx.x;
    const int tl  = (t < 112) ? t : (t - 112);
    const int g   = (t < 112) ? 0 : 4;
    const int h   = tl >> 2;
    const int q   = tl & 3;
    const int cb  = h * SROW + 7 * q;
    const u32 NEG1 = 0xBC00BC00u;         // (-1.h, -1.h)

    // zero all 4 tiles (halo stays zero forever)
    for (int i = t; i < 4 * TROWS * SROW; i += NT)
        (&xs[0][0])[i] = 0u;

    {   // stage W: 16ch x 9kk x 8 pairs = 1152 u32, coalesced
        const u32* wp = g_wq + (size_t)(cq * CPC * 9) * NFP + fp0;
        for (int i = t; i < CPC * 9 * 8; i += NT) {
            int p  = i & 7;
            int ck = i >> 3;
            ws[i] = wp[(size_t)ck * NFP + p];
        }
    }

    u32 offsA, offsB;
    {
        u32 o[4];
#pragma unroll
        for (int j = 0; j < 4; ++j) {
            int l = t + NT * j;
            if (l < LSP) {
                int hh = l / HW;
                int ww = l - hh * HW;
                o[j] = (hh + 1) * SROW + (ww + 1);
            } else o[j] = 0;
        }
        offsA = o[0] | (o[1] << 16);
        offsB = o[2] | (o[3] << 16);
    }

    const u32* xg = g_xd + ((size_t)b * CIN + (size_t)cq * CPC) * LSP;

    // prefetch channel pair 0 (channels 0,1)
    u32 r[8];
#pragma unroll
    for (int j = 0; j < 3; ++j) {
        r[j]     = xg[t + NT * j];
        r[4 + j] = xg[LSP + t + NT * j];
    }
    if (t < 112) { r[3] = xg[t + NT * 3]; r[7] = xg[LSP + t + NT * 3]; }

    u32 acc[4][7];
#pragma unroll
    for (int p = 0; p < 4; ++p)
#pragma unroll
        for (int j = 0; j < 7; ++j) acc[p][j] = 0u;

    __syncthreads();   // tile zero + ws visible

#define COMPUTE(BUFP, CH)                                                      \
    {                                                                          \
        const u32* wrow = ws + (CH) * 72;                                      \
        _Pragma("unroll")                                                      \
        for (int kh = 0; kh < 3; ++kh) {                                       \
            u32 xv[9];                                                         \
            _Pragma("unroll")                                                  \
            for (int i = 0; i < 9; ++i)                                        \
                xv[i] = xs[BUFP][cb + kh * SROW + i];                          \
            _Pragma("unroll")                                                  \
            for (int kw = 0; kw < 3; ++kw) {                                   \
                uint4 wv = *reinterpret_cast<const uint4*>(                    \
                    &wrow[(kh * 3 + kw) * 8 + g]);                             \
                _Pragma("unroll")                                              \
                for (int j = 0; j < 7; ++j) {                                  \
                    absdiff_acc(acc[0][j], xv[j + kw], NEG1, wv.x);            \
                    absdiff_acc(acc[1][j], xv[j + kw], NEG1, wv.y);            \
                    absdiff_acc(acc[2][j], xv[j + kw], NEG1, wv.z);            \
                    absdiff_acc(acc[3][j], xv[j + kw], NEG1, wv.w);            \
                }                                                              \
            }                                                                  \
        }                                                                      \
    }

#pragma unroll 1
    for (int p = 0; p < CPC / 2; ++p) {
        const int b0 = 2 * (p & 1);       // buffer group: {0,1} or {2,3}
        // store current pair
        xs[b0][offsA & 0xFFFF]     = r[0];
        xs[b0][offsA >> 16]        = r[1];
        xs[b0][offsB & 0xFFFF]     = r[2];
        xs[b0 + 1][offsA & 0xFFFF] = r[4];
        xs[b0 + 1][offsA >> 16]    = r[5];
        xs[b0 + 1][offsB & 0xFFFF] = r[6];
        if (t < 112) {
            xs[b0][offsB >> 16]     = r[3];
            xs[b0 + 1][offsB >> 16] = r[7];
        }
        // prefetch next pair
        if (p + 1 < CPC / 2) {
            const u32* xn = xg + (size_t)(2 * p + 2) * LSP;
#pragma unroll
            for (int j = 0; j < 3; ++j) {
                r[j]     = xn[t + NT * j];
                r[4 + j] = xn[LSP + t + NT * j];
            }
            if (t < 112) { r[3] = xn[t + NT * 3]; r[7] = xn[LSP + t + NT * 3]; }
        }
        __syncthreads();   // pair visible; prior use of this group done

        COMPUTE(b0,     2 * p)
        COMPUTE(b0 + 1, 2 * p + 1)
    }
#undef COMPUTE

    // epilogue: promote fp16x2 -> 2x fp32, RED-accumulate negated partials
    float* ob = out + ((size_t)b * FOUT + 2 * (fp0 + g)) * LSP + h * HW + 7 * q;
#pragma unroll
    for (int p = 0; p < 4; ++p) {
        float* o0 = ob + (size_t)(2 * p) * LSP;
        float* o1 = o0 + LSP;
#pragma unroll
        for (int j = 0; j < 7; ++j) {
            float2 v = __half22float2(*reinterpret_cast<__half2*>(&acc[p][j]));
            atomicAdd(&o0[j], -v.x);
            atomicAdd(&o1[j], -v.y);
        }
    }
}

extern "C" void kernel_launch(void* const* d_in, const int* in_sizes, int n_in,
                              void* d_out, int out_size) {
    const float* x = (const float*)d_in[0];
    const float* W = (const float*)d_in[1];
    if (n_in >= 2 && in_sizes[0] == FOUT * CIN * 9 && in_sizes[1] == BATCH * CIN * LSP) {
        const float* tmp = x; x = W; W = tmp;
    }
    float* out = (float*)d_out;

    prep_x_kernel<<<BATCH * CIN * LSP / 1024, 1024>>>(x);
    prep_w_kernel<<<(CIN * 9 * NFP + 255) / 256, 256>>>(W);
    zero_out_kernel<<<392, 1024>>>((float4*)out);

    dim3 grid(FOUT / 16, BATCH, NCHQ);   // 8 x 16 x 8 = 1024 CTAs
    adder2d_kernel<<<grid, NT>>>(out);
}